// round 1
// baseline (speedup 1.0000x reference)
#include <cuda_runtime.h>
#include <math.h>

// Problem shape (fixed): B=8, C=64, T=16, H=64, W=64, text_dim=768
#define NB 8
#define NC 64
#define NT 16
#define HW 4096          // H*W
#define HW4 1024         // HW/4 (float4 units)
#define TD 768
#define NBC (NB*NC)      // 512

// Scratch for fused per-(b,c) 16x16 matrices M = D^T diag(w) D  (symmetric)
__device__ float g_M[NBC * NT * NT];   // 512 KB

// ---------------------------------------------------------------------------
// Kernel 1: gates + fused matrix build.  One block per (b,c), 256 threads.
// ---------------------------------------------------------------------------
__global__ __launch_bounds__(256) void gate_matrix_kernel(
    const float* __restrict__ E,    // (B, 768)
    const float* __restrict__ Wf,   // (C*T, 768)
    const float* __restrict__ bf)   // (C*T,)
{
    __shared__ float sw[NT];
    __shared__ float sD[NT][NT];    // sD[k][t] = DCT-II ortho matrix

    const int bc = blockIdx.x;
    const int b = bc >> 6;          // / NC
    const int c = bc & 63;          // % NC
    const int warp = threadIdx.x >> 5;
    const int lane = threadIdx.x & 31;

    // 8 warps compute the 16 gate logits (768-dots), 2 per warp
    for (int g = warp; g < NT; g += 8) {
        const int j = c * NT + g;
        const float* e  = E  + (size_t)b * TD;
        const float* wr = Wf + (size_t)j * TD;
        float s = 0.0f;
        #pragma unroll 4
        for (int d = lane; d < TD; d += 32) s = fmaf(e[d], wr[d], s);
        #pragma unroll
        for (int o = 16; o; o >>= 1) s += __shfl_xor_sync(0xffffffffu, s, o);
        if (lane == 0) {
            float z = s + bf[j];
            sw[g] = 1.0f / (1.0f + expf(-z));
        }
    }

    // Build D: thread i -> D[i/16][i%16]
    {
        const int k = threadIdx.x >> 4;
        const int t = threadIdx.x & 15;
        const float sc = (k == 0) ? 0.25f : 0.35355339059327373f; // sqrt(1/16), sqrt(2/16)
        sD[k][t] = cosf(3.14159265358979323846f * ((float)t + 0.5f) * (float)k / 16.0f) * sc;
    }
    __syncthreads();

    // M[to][ti] = sum_k D[k][to] * w[k] * D[k][ti]   (256 threads, 1 entry each)
    {
        const int to = threadIdx.x >> 4;
        const int ti = threadIdx.x & 15;
        float acc = 0.0f;
        #pragma unroll
        for (int k = 0; k < NT; k++)
            acc = fmaf(sD[k][to] * sw[k], sD[k][ti], acc);
        g_M[(size_t)bc * 256 + threadIdx.x] = acc;
    }
}

// ---------------------------------------------------------------------------
// Kernel 2: streaming modulation.  Grid (512, 4); block 256 threads.
// Each thread: one float4 column-group (4 spatial columns), full 16x16 matvec.
// ---------------------------------------------------------------------------
__global__ __launch_bounds__(256) void mod_kernel(
    const float4* __restrict__ r,   // (B,C,T,H,W) as float4 over W
    float4* __restrict__ out)
{
    // sM[k][t4] holds M[k][4*t4 .. 4*t4+3] (M symmetric, so row == column)
    __shared__ float4 sM[NT][4];

    const int bc = blockIdx.x;
    if (threadIdx.x < 64) {
        const float4* gm = (const float4*)g_M;
        ((float4*)sM)[threadIdx.x] = gm[(size_t)bc * 64 + threadIdx.x];
    }
    __syncthreads();

    const int u = blockIdx.y * 256 + threadIdx.x;          // [0, 1024)
    const size_t base = (size_t)bc * (NT * HW4) + u;

    // Front-batched loads: 16 independent LDG.128 (MLP=16)
    float4 x[NT];
    #pragma unroll
    for (int k = 0; k < NT; k++)
        x[k] = r[base + (size_t)k * HW4];

    // y[t] = sum_k M[t][k] * x[k], 4 output rows at a time
    #pragma unroll
    for (int t4 = 0; t4 < 4; t4++) {
        float4 ya = make_float4(0.f, 0.f, 0.f, 0.f);
        float4 yb = ya, yc = ya, yd = ya;
        #pragma unroll
        for (int k = 0; k < NT; k++) {
            const float4 m = sM[k][t4];   // broadcast LDS.128
            const float4 xv = x[k];
            ya.x = fmaf(m.x, xv.x, ya.x); ya.y = fmaf(m.x, xv.y, ya.y);
            ya.z = fmaf(m.x, xv.z, ya.z); ya.w = fmaf(m.x, xv.w, ya.w);
            yb.x = fmaf(m.y, xv.x, yb.x); yb.y = fmaf(m.y, xv.y, yb.y);
            yb.z = fmaf(m.y, xv.z, yb.z); yb.w = fmaf(m.y, xv.w, yb.w);
            yc.x = fmaf(m.z, xv.x, yc.x); yc.y = fmaf(m.z, xv.y, yc.y);
            yc.z = fmaf(m.z, xv.z, yc.z); yc.w = fmaf(m.z, xv.w, yc.w);
            yd.x = fmaf(m.w, xv.x, yd.x); yd.y = fmaf(m.w, xv.y, yd.y);
            yd.z = fmaf(m.w, xv.z, yd.z); yd.w = fmaf(m.w, xv.w, yd.w);
        }
        out[base + (size_t)(t4 * 4 + 0) * HW4] = ya;
        out[base + (size_t)(t4 * 4 + 1) * HW4] = yb;
        out[base + (size_t)(t4 * 4 + 2) * HW4] = yc;
        out[base + (size_t)(t4 * 4 + 3) * HW4] = yd;
    }
}

// ---------------------------------------------------------------------------
extern "C" void kernel_launch(void* const* d_in, const int* in_sizes, int n_in,
                              void* d_out, int out_size)
{
    const float* r  = (const float*)d_in[0];   // (8,64,16,64,64)
    const float* E  = (const float*)d_in[1];   // (8,768)
    const float* Wf = (const float*)d_in[2];   // (1024,768)
    const float* bf = (const float*)d_in[3];   // (1024,)
    float* out = (float*)d_out;

    gate_matrix_kernel<<<NBC, 256>>>(E, Wf, bf);

    dim3 grid(NBC, 4);
    mod_kernel<<<grid, 256>>>((const float4*)r, (float4*)out);
}

// round 2
// speedup vs baseline: 1.3238x; 1.3238x over previous
#include <cuda_runtime.h>
#include <math.h>

// Problem shape (fixed): B=8, C=64, T=16, H=64, W=64, text_dim=768
#define NB 8
#define NC 64
#define NT 16
#define HW4 1024         // H*W/4 (float4 / ulonglong2 units per T-plane)
#define TD 768
#define NBC (NB*NC)      // 512

// Per-(b,c) fused 16x16 matrix M = D^T diag(w) D, stored as DUPLICATED f32x2
// pairs: g_M2[bc][t][k] = (M[t][k], M[t][k])  -> ready as fma.rn.f32x2 multiplier.
__device__ float2 g_M2[NBC * NT * NT];   // 1 MB

// ---------------------------------------------------------------------------
// Kernel 1: gates + fused matrix build.  One block per (b,c), 256 threads.
// ---------------------------------------------------------------------------
__global__ __launch_bounds__(256) void gate_matrix_kernel(
    const float* __restrict__ E,    // (B, 768)
    const float* __restrict__ Wf,   // (C*T, 768)
    const float* __restrict__ bf)   // (C*T,)
{
    __shared__ float sw[NT];
    __shared__ float sD[NT][NT];    // sD[k][t] = DCT-II ortho matrix

    const int bc = blockIdx.x;
    const int b = bc >> 6;
    const int c = bc & 63;
    const int warp = threadIdx.x >> 5;
    const int lane = threadIdx.x & 31;

    // 8 warps compute the 16 gate logits (768-dots via float4), 2 per warp
    for (int g = warp; g < NT; g += 8) {
        const int j = c * NT + g;
        const float4* e4 = (const float4*)(E  + (size_t)b * TD);
        const float4* w4 = (const float4*)(Wf + (size_t)j * TD);
        float s = 0.0f;
        #pragma unroll
        for (int d = lane; d < TD / 4; d += 32) {
            const float4 ev = e4[d];
            const float4 wv = w4[d];
            s = fmaf(ev.x, wv.x, s);
            s = fmaf(ev.y, wv.y, s);
            s = fmaf(ev.z, wv.z, s);
            s = fmaf(ev.w, wv.w, s);
        }
        #pragma unroll
        for (int o = 16; o; o >>= 1) s += __shfl_xor_sync(0xffffffffu, s, o);
        if (lane == 0) {
            float z = s + bf[j];
            sw[g] = 1.0f / (1.0f + expf(-z));
        }
    }

    // Build D: thread i -> D[i/16][i%16]
    {
        const int k = threadIdx.x >> 4;
        const int t = threadIdx.x & 15;
        const float sc = (k == 0) ? 0.25f : 0.35355339059327373f; // sqrt(1/16), sqrt(2/16)
        sD[k][t] = cosf(3.14159265358979323846f * ((float)t + 0.5f) * (float)k / 16.0f) * sc;
    }
    __syncthreads();

    // M[to][ti] = sum_k D[k][to] * w[k] * D[k][ti]; write duplicated pair
    {
        const int to = threadIdx.x >> 4;
        const int ti = threadIdx.x & 15;
        float acc = 0.0f;
        #pragma unroll
        for (int k = 0; k < NT; k++)
            acc = fmaf(sD[k][to] * sw[k], sD[k][ti], acc);
        g_M2[(size_t)bc * 256 + threadIdx.x] = make_float2(acc, acc);
    }
}

// ---------------------------------------------------------------------------
// Kernel 2: streaming modulation with packed fma.rn.f32x2 (SASS FFMA2).
// Grid (512, 4); 256 threads. Each thread: one float4 column-group,
// resident-x (16 x LDG.128, MLP=16), streamed-y (store right after each row).
// ---------------------------------------------------------------------------
__global__ __launch_bounds__(256) void mod_kernel(
    const ulonglong2* __restrict__ r,   // float4 planes viewed as 2x f32x2
    ulonglong2* __restrict__ out)
{
    // sM2[t][k2] = ( pair(M[t][2k2]), pair(M[t][2k2+1]) )  -- 2 KB
    __shared__ ulonglong2 sM2[NT][NT / 2];

    const int bc = blockIdx.x;
    if (threadIdx.x < 128) {
        ((ulonglong2*)sM2)[threadIdx.x] =
            ((const ulonglong2*)g_M2)[(size_t)bc * 128 + threadIdx.x];
    }
    __syncthreads();

    const int u = blockIdx.y * 256 + threadIdx.x;          // [0, 1024)
    const size_t base = (size_t)bc * (NT * HW4) + u;

    // Front-batched loads: 16 independent LDG.128 (MLP=16)
    ulonglong2 x[NT];
    #pragma unroll
    for (int k = 0; k < NT; k++)
        x[k] = r[base + (size_t)k * HW4];

    // y[t] = sum_k M[t][k] * x[k]  -- two f32x2 accumulators per row
    #pragma unroll
    for (int t = 0; t < NT; t++) {
        unsigned long long alo = 0ull, ahi = 0ull;   // (0.f,0.f) packed
        #pragma unroll
        for (int k2 = 0; k2 < NT / 2; k2++) {
            const ulonglong2 m = sM2[t][k2];         // broadcast LDS.128
            asm("fma.rn.f32x2 %0, %1, %2, %0;" : "+l"(alo) : "l"(m.x), "l"(x[2*k2].x));
            asm("fma.rn.f32x2 %0, %1, %2, %0;" : "+l"(ahi) : "l"(m.x), "l"(x[2*k2].y));
            asm("fma.rn.f32x2 %0, %1, %2, %0;" : "+l"(alo) : "l"(m.y), "l"(x[2*k2+1].x));
            asm("fma.rn.f32x2 %0, %1, %2, %0;" : "+l"(ahi) : "l"(m.y), "l"(x[2*k2+1].y));
        }
        ulonglong2 y; y.x = alo; y.y = ahi;
        out[base + (size_t)t * HW4] = y;
    }
}

// ---------------------------------------------------------------------------
extern "C" void kernel_launch(void* const* d_in, const int* in_sizes, int n_in,
                              void* d_out, int out_size)
{
    const float* r  = (const float*)d_in[0];   // (8,64,16,64,64)
    const float* E  = (const float*)d_in[1];   // (8,768)
    const float* Wf = (const float*)d_in[2];   // (1024,768)
    const float* bf = (const float*)d_in[3];   // (1024,)
    float* out = (float*)d_out;

    gate_matrix_kernel<<<NBC, 256>>>(E, Wf, bf);

    dim3 grid(NBC, 4);
    mod_kernel<<<grid, 256>>>((const ulonglong2*)r, (ulonglong2*)out);
}